// round 16
// baseline (speedup 1.0000x reference)
#include <cuda_runtime.h>
#include <cuda_fp16.h>

#define NN 100000
#define EMAX 700000
#define CH 128
#define BM 64

typedef unsigned long long ull;
typedef unsigned int u32;

// ---- smem byte offsets (layer kernel) ----
#define OFF_BIAS 0
#define OFF_WLH 512
#define OFF_WRH (OFF_WLH + 32768)
#define OFF_AGH (OFF_WRH + 32768)
#define OFF_AXH (OFF_AGH + 16384)
#define SMEM_TOTAL (OFF_AXH + 16384)   // 98816 bytes -> 2 CTAs/SM

__device__ __align__(128) __half g_aggh[(size_t)NN * CH]; // fp16 mean-aggregated
__device__ __align__(128) __half g_xh[(size_t)NN * CH];   // fp16 copy of x
__device__ __align__(128) __half g_hh[(size_t)NN * CH];   // fp16 hidden layer
__device__ int g_deg[NN];
__device__ int g_off[NN + 1];
__device__ int g_cursor[NN];
__device__ int g_bsum[128];
__device__ int g_ssrc[EMAX];
__device__ int g_is64;

// ---------------- helpers ----------------
__device__ __forceinline__ u32 smem_u32(const void* p) {
    u32 a;
    asm("{ .reg .u64 t; cvta.to.shared.u64 t, %1; cvt.u32.u64 %0, t; }"
        : "=r"(a) : "l"(p));
    return a;
}
__device__ __forceinline__ void ldsm4(u32* r, u32 addr) {
    asm volatile("ldmatrix.sync.aligned.m8n8.x4.shared.b16 {%0,%1,%2,%3}, [%4];"
                 : "=r"(r[0]), "=r"(r[1]), "=r"(r[2]), "=r"(r[3]) : "r"(addr));
}
__device__ __forceinline__ void mma16816(float* d, const u32* a, const u32* b) {
    asm volatile(
        "mma.sync.aligned.m16n8k16.row.col.f32.f16.f16.f32 "
        "{%0,%1,%2,%3}, {%4,%5,%6,%7}, {%8,%9}, {%0,%1,%2,%3};"
        : "+f"(d[0]), "+f"(d[1]), "+f"(d[2]), "+f"(d[3])
        : "r"(a[0]), "r"(a[1]), "r"(a[2]), "r"(a[3]), "r"(b[0]), "r"(b[1]));
}
__device__ __forceinline__ ull pack4h(__half a, __half b, __half c, __half d) {
    u32 lo = ((u32)__half_as_ushort(b) << 16) | __half_as_ushort(a);
    u32 hi = ((u32)__half_as_ushort(d) << 16) | __half_as_ushort(c);
    return ((ull)hi << 32) | lo;
}
// byte offset of 4 fp16 at (row r, group-of-4 q); 256B rows, 16B-chunk XOR swizzle.
__device__ __forceinline__ u32 swz_off(int r, int q) {
    return ((u32)r << 8) + ((u32)(((q >> 1) ^ (r & 7))) << 4) + ((u32)(q & 1) << 3);
}
__device__ __forceinline__ void round_store_w(char* hi, int r, int q, float4 v) {
    *(ull*)(hi + swz_off(r, q)) = pack4h(
        __float2half_rn(v.x), __float2half_rn(v.y),
        __float2half_rn(v.z), __float2half_rn(v.w));
}
__device__ __forceinline__ __half2 as_h2(u32 v) { return *(__half2*)&v; }

// ---------------- graph preprocessing (CSR by dst, once per replay) ----------------
__global__ void zero_detect_kernel(const int* __restrict__ ei, int E, int n) {
    int i = blockIdx.x * blockDim.x + threadIdx.x;
    if (i < n) g_deg[i] = 0;
    if (blockIdx.x == 0) {
        __shared__ int s_any;
        if (threadIdx.x == 0) s_any = 0;
        __syncthreads();
        int nchk = E < 1024 ? E : 1024;
        int acc = 0;
        for (int e = threadIdx.x; e < nchk; e += blockDim.x)
            acc |= ei[2 * e + 1];
        if (acc) atomicOr(&s_any, 1);
        __syncthreads();
        if (threadIdx.x == 0) g_is64 = (s_any ? 0 : 1);
    }
}

// histogram + (fused) x -> fp16 conversion
__global__ void hist_convert_kernel(const int* __restrict__ ei, int E,
                                    const float* __restrict__ x, int n) {
    int gid = blockIdx.x * blockDim.x + threadIdx.x;
    if (gid < E) {
        int dst = g_is64 ? ei[2 * (E + gid)] : ei[E + gid];
        atomicAdd(&g_deg[dst], 1);
    }
    int total4 = n * 32;
    int stride = gridDim.x * blockDim.x;
    uint2* xh2 = (uint2*)g_xh;
    for (int i = gid; i < total4; i += stride) {
        float4 v = ((const float4*)x)[i];
        __half2 a = __floats2half2_rn(v.x, v.y);
        __half2 b = __floats2half2_rn(v.z, v.w);
        uint2 u;
        u.x = *(u32*)&a;
        u.y = *(u32*)&b;
        xh2[i] = u;
    }
}

// scan stage A: per-block (1024 elems) sums
__global__ void scan_a_kernel(int n) {
    __shared__ int ssum[256];
    int tid = threadIdx.x;
    int base = blockIdx.x * 1024 + tid * 4;
    int s = 0;
#pragma unroll
    for (int j = 0; j < 4; ++j) {
        int i = base + j;
        if (i < n) s += g_deg[i];
    }
    ssum[tid] = s;
    __syncthreads();
    for (int off = 128; off > 0; off >>= 1) {
        if (tid < off) ssum[tid] += ssum[tid + off];
        __syncthreads();
    }
    if (tid == 0) g_bsum[blockIdx.x] = ssum[0];
}

// scan stage C: block-sum prefix + per-block exclusive scan; writes g_off/g_cursor.
__global__ void scan_c_kernel(int n) {
    __shared__ int sdata[256];
    __shared__ int s_boff;
    int tid = threadIdx.x;

    int partial = 0;
    for (int b = tid; b < (int)blockIdx.x; b += 256) partial += g_bsum[b];
    sdata[tid] = partial;
    __syncthreads();
    for (int off = 128; off > 0; off >>= 1) {
        if (tid < off) sdata[tid] += sdata[tid + off];
        __syncthreads();
    }
    if (tid == 0) s_boff = sdata[0];
    __syncthreads();

    int base = blockIdx.x * 1024 + tid * 4;
    int v[4];
    int tsum = 0;
#pragma unroll
    for (int j = 0; j < 4; ++j) {
        int i = base + j;
        v[j] = (i < n) ? g_deg[i] : 0;
        tsum += v[j];
    }
    sdata[tid] = tsum;
    __syncthreads();
    for (int off = 1; off < 256; off <<= 1) {
        int t = (tid >= off) ? sdata[tid - off] : 0;
        __syncthreads();
        sdata[tid] += t;
        __syncthreads();
    }
    int excl = sdata[tid] - tsum + s_boff;
#pragma unroll
    for (int j = 0; j < 4; ++j) {
        int i = base + j;
        if (i < n) {
            g_off[i] = excl;
            g_cursor[i] = excl;
            excl += v[j];
        }
    }
    if (blockIdx.x == gridDim.x - 1 && tid == 255)
        g_off[n] = s_boff + sdata[255];
}

__global__ void reorder_kernel(const int* __restrict__ ei, int E) {
    int e = blockIdx.x * blockDim.x + threadIdx.x;
    if (e >= E) return;
    int src, dst;
    if (g_is64) {
        src = ei[2 * e];
        dst = ei[2 * (E + e)];
    } else {
        src = ei[e];
        dst = ei[E + e];
    }
    int pos = atomicAdd(&g_cursor[dst], 1);
    g_ssrc[pos] = src;
}

// ---------------- mean aggregation: one warp per dst, predicated 8-wide batches ----
// All 8 row-loads of a batch issue unconditionally (indices clamped to a safe
// edge), only accumulation is predicated -> MLP=8, no serial tail.
__global__ void agg_kernel(const __half* __restrict__ feat, int n) {
    int gid = blockIdx.x * blockDim.x + threadIdx.x;
    int d = gid >> 5, lane = gid & 31;
    if (d >= n) return;
    int s = g_off[d], e = g_off[d + 1];
    const uint2* f2 = (const uint2*)feat;
    float4 acc = make_float4(0.f, 0.f, 0.f, 0.f);

    if (e > s) {
        for (int base = s; base < e; base += 8) {
            int idx[8];
#pragma unroll
            for (int j = 0; j < 8; ++j) {
                int p = base + j;
                idx[j] = g_ssrc[p < e ? p : s];   // clamped safe index
            }
            uint2 u[8];
#pragma unroll
            for (int j = 0; j < 8; ++j)
                u[j] = f2[(size_t)idx[j] * 32 + lane];
#pragma unroll
            for (int j = 0; j < 8; ++j) {
                if (base + j < e) {
                    float2 a = __half22float2(as_h2(u[j].x));
                    float2 b = __half22float2(as_h2(u[j].y));
                    acc.x += a.x; acc.y += a.y; acc.z += b.x; acc.w += b.y;
                }
            }
        }
        float inv = 1.0f / (float)(e - s);
        acc.x *= inv; acc.y *= inv; acc.z *= inv; acc.w *= inv;
    }
    __half2 h0 = __floats2half2_rn(acc.x, acc.y);
    __half2 h1 = __floats2half2_rn(acc.z, acc.w);
    uint2 u;
    u.x = *(u32*)&h0;
    u.y = *(u32*)&h1;
    ((uint2*)g_aggh)[(size_t)d * 32 + lane] = u;   // mean pre-folded, fp16
}

// ---------------- HMMA fused SAGE layer (all-fp16, 2 CTAs/SM) ----------------
// out = act( aggh @ Wl^T + bl + A2h @ Wr^T )
__device__ __forceinline__ void mma_pass1(u32 abh, u32 wbh,
                                          float acc[2][4][4],
                                          const u32* rowA256, u32 rowA7, u32 kbitA,
                                          const u32* rw256, const u32* rw7, u32 kgrpW) {
#pragma unroll
    for (int ks = 0; ks < 8; ++ks) {
        u32 ks2 = (u32)(ks << 1);
        u32 ah[2][4], wh[2][4];
        u32 ca = ((ks2 | kbitA) ^ rowA7) << 4;
#pragma unroll
        for (int mt = 0; mt < 2; ++mt)
            ldsm4(ah[mt], abh + rowA256[mt] + ca);
#pragma unroll
        for (int nt2 = 0; nt2 < 2; ++nt2) {
            u32 cw = ((ks2 | kgrpW) ^ rw7[nt2]) << 4;
            ldsm4(wh[nt2], wbh + rw256[nt2] + cw);
        }
#pragma unroll
        for (int mt = 0; mt < 2; ++mt)
#pragma unroll
            for (int nt = 0; nt < 4; ++nt)
                mma16816(acc[mt][nt], ah[mt], &wh[nt >> 1][(nt & 1) * 2]);
    }
}

__global__ void __launch_bounds__(256, 2)
layer_kernel(const __half* __restrict__ A2h,
             const float* __restrict__ Wl,
             const float* __restrict__ Wr,
             const float* __restrict__ bl,
             float* __restrict__ outf,
             __half* __restrict__ outh,
             int n, int apply_sig, int ntiles) {
    extern __shared__ char sm[];
    u32 smb = smem_u32(sm);
    float* sBias = (float*)(sm + OFF_BIAS);
    int tid = threadIdx.x, wid = tid >> 5, lane = tid & 31;
    int warp_m = wid & 1, warp_n = wid >> 1;

    // Round both weight matrices ([n][k], 128x128) to fp16.
    for (int idx = tid; idx < 128 * 32; idx += 256) {
        int r = idx >> 5, q = idx & 31;
        round_store_w(sm + OFF_WLH, r, q, ((const float4*)Wl)[idx]);
        round_store_w(sm + OFF_WRH, r, q, ((const float4*)Wr)[idx]);
    }
    if (tid < 128) sBias[tid] = bl[tid];

    // ldmatrix address precomputation.
    u32 rowA256[2], rowA7;
    {
        int ra0 = warp_m * 32 + (lane & 15);
        rowA256[0] = (u32)(ra0 << 8);
        rowA256[1] = (u32)((ra0 + 16) << 8);
        rowA7 = (u32)(ra0 & 7);
    }
    u32 kbitA = (u32)(lane >> 4);
    u32 rw256[2], rw7[2];
    u32 kgrpW = (u32)((lane >> 3) & 1);
    {
        int base = warp_n * 32 + (lane & 7) + ((lane >> 4) << 3);
#pragma unroll
        for (int nt2 = 0; nt2 < 2; ++nt2) {
            int rw = base + nt2 * 16;
            rw256[nt2] = (u32)(rw << 8);
            rw7[nt2] = (u32)(rw & 7);
        }
    }
    int g = lane >> 2, c2 = (lane & 3) * 2;

    const uint2* ag2 = (const uint2*)g_aggh;
    const uint2* x2 = (const uint2*)A2h;
    const uint2 uz = make_uint2(0u, 0u);

    uint2 va[8], vx[8];
    int tile = blockIdx.x;

    if (tile < ntiles) {
        int row0 = tile * BM;
#pragma unroll
        for (int j = 0; j < 8; ++j) {
            int idx = tid + j * 256;
            int row = row0 + (idx >> 5);
            va[j] = (row < n) ? ag2[(size_t)row * 32 + (idx & 31)] : uz;
            vx[j] = (row < n) ? x2[(size_t)row * 32 + (idx & 31)] : uz;
        }
    }

    for (; tile < ntiles; tile += gridDim.x) {
        __syncthreads();   // prior tile MMA done reading A buffers (covers W on 1st)
#pragma unroll
        for (int j = 0; j < 8; ++j) {
            int idx = tid + j * 256;
            int r = idx >> 5, q = idx & 31;
            u32 off = swz_off(r, q);
            *(uint2*)(sm + OFF_AGH + off) = va[j];
            *(uint2*)(sm + OFF_AXH + off) = vx[j];
        }
        __syncthreads();

        // Prefetch next tile's A registers; LDG latency hides under MMA below.
        int next = tile + gridDim.x;
        if (next < ntiles) {
            int row0 = next * BM;
#pragma unroll
            for (int j = 0; j < 8; ++j) {
                int idx = tid + j * 256;
                int row = row0 + (idx >> 5);
                va[j] = (row < n) ? ag2[(size_t)row * 32 + (idx & 31)] : uz;
                vx[j] = (row < n) ? x2[(size_t)row * 32 + (idx & 31)] : uz;
            }
        }

        float acc[2][4][4];
#pragma unroll
        for (int mt = 0; mt < 2; ++mt)
#pragma unroll
            for (int nt = 0; nt < 4; ++nt)
#pragma unroll
                for (int i = 0; i < 4; ++i) acc[mt][nt][i] = 0.f;

        mma_pass1(smb + OFF_AGH, smb + OFF_WLH,
                  acc, rowA256, rowA7, kbitA, rw256, rw7, kgrpW);
        mma_pass1(smb + OFF_AXH, smb + OFF_WRH,
                  acc, rowA256, rowA7, kbitA, rw256, rw7, kgrpW);

        // epilogue
        int row0 = tile * BM;
#pragma unroll
        for (int mt = 0; mt < 2; ++mt) {
#pragma unroll
            for (int half = 0; half < 2; ++half) {
                int row = row0 + warp_m * 32 + mt * 16 + g + half * 8;
                if (row < n) {
#pragma unroll
                    for (int nt = 0; nt < 4; ++nt) {
                        int col = warp_n * 32 + nt * 8 + c2;
                        float2 v;
                        v.x = acc[mt][nt][half * 2 + 0] + sBias[col];
                        v.y = acc[mt][nt][half * 2 + 1] + sBias[col + 1];
                        if (apply_sig) {
                            v.x = 1.0f / (1.0f + __expf(-v.x));
                            v.y = 1.0f / (1.0f + __expf(-v.y));
                            __half2 hv = __floats2half2_rn(v.x, v.y);
                            *(__half2*)(outh + (size_t)row * CH + col) = hv;
                        } else {
                            *(float2*)(outf + (size_t)row * CH + col) = v;
                        }
                    }
                }
            }
        }
    }
}

extern "C" void kernel_launch(void* const* d_in, const int* in_sizes, int n_in,
                              void* d_out, int out_size) {
    const float* x   = (const float*)d_in[0];
    const int*   ei  = (const int*)d_in[1];
    const float* W1l = (const float*)d_in[2];
    const float* b1l = (const float*)d_in[3];
    const float* W1r = (const float*)d_in[4];
    const float* W2l = (const float*)d_in[5];
    const float* b2l = (const float*)d_in[6];
    const float* W2r = (const float*)d_in[7];
    float* out = (float*)d_out;

    int n = in_sizes[0] / CH;   // 100000
    int E = in_sizes[1] / 2;    // 625000
    if (E > EMAX) E = EMAX;

    __half* xh_ptr = nullptr;
    __half* hh_ptr = nullptr;
    cudaGetSymbolAddress((void**)&xh_ptr, g_xh);
    cudaGetSymbolAddress((void**)&hh_ptr, g_hh);

    cudaFuncSetAttribute(layer_kernel,
                         cudaFuncAttributeMaxDynamicSharedMemorySize, SMEM_TOTAL);

    int ntiles = (n + BM - 1) / BM;
    int grid_layer = ntiles < 296 ? ntiles : 296;   // 2 CTAs/SM
    int grid_edge = (E + 255) / 256;
    int nblk = (n + 1023) / 1024;
    int grid_agg = (int)(((long long)n * 32 + 255) / 256);

    // CSR preprocessing + x->fp16 (once; reused by both layers)
    zero_detect_kernel<<<(n + 255) / 256, 256>>>(ei, E, n);
    hist_convert_kernel<<<grid_edge, 256>>>(ei, E, x, n);
    scan_a_kernel<<<nblk, 256>>>(n);
    scan_c_kernel<<<nblk, 256>>>(n);
    reorder_kernel<<<grid_edge, 256>>>(ei, E);

    // Layer 1
    agg_kernel<<<grid_agg, 256>>>(xh_ptr, n);
    layer_kernel<<<grid_layer, 256, SMEM_TOTAL>>>(xh_ptr, W1l, W1r, b1l,
                                                  nullptr, hh_ptr, n, 1, ntiles);

    // Layer 2
    agg_kernel<<<grid_agg, 256>>>(hh_ptr, n);
    layer_kernel<<<grid_layer, 256, SMEM_TOTAL>>>(hh_ptr, W2l, W2r, b2l,
                                                  out, nullptr, n, 0, ntiles);
}

// round 17
// speedup vs baseline: 1.0923x; 1.0923x over previous
#include <cuda_runtime.h>
#include <cuda_fp16.h>

#define NN 100000
#define EMAX 700000
#define CH 128
#define BM 64

typedef unsigned long long ull;
typedef unsigned int u32;

// ---- smem byte offsets (layer kernel) ----
#define OFF_BIAS 0
#define OFF_WLH 512
#define OFF_WRH (OFF_WLH + 32768)
#define OFF_AGH (OFF_WRH + 32768)
#define OFF_AXH (OFF_AGH + 16384)
#define SMEM_TOTAL (OFF_AXH + 16384)   // 98816 bytes -> 2 CTAs/SM

__device__ __align__(128) __half g_aggh[(size_t)NN * CH]; // fp16 mean-aggregated
__device__ __align__(128) __half g_xh[(size_t)NN * CH];   // fp16 copy of x
__device__ __align__(128) __half g_hh[(size_t)NN * CH];   // fp16 hidden layer
__device__ int g_deg[NN];        // ZERO invariant: zeroed at end of reorder_kernel
__device__ int g_off[NN + 1];
__device__ int g_cursor[NN];
__device__ int g_bsum[128];
__device__ int g_ssrc[EMAX];
__device__ int g_is64;

// ---------------- helpers ----------------
__device__ __forceinline__ u32 smem_u32(const void* p) {
    u32 a;
    asm("{ .reg .u64 t; cvta.to.shared.u64 t, %1; cvt.u32.u64 %0, t; }"
        : "=r"(a) : "l"(p));
    return a;
}
__device__ __forceinline__ void ldsm4(u32* r, u32 addr) {
    asm volatile("ldmatrix.sync.aligned.m8n8.x4.shared.b16 {%0,%1,%2,%3}, [%4];"
                 : "=r"(r[0]), "=r"(r[1]), "=r"(r[2]), "=r"(r[3]) : "r"(addr));
}
__device__ __forceinline__ void mma16816(float* d, const u32* a, const u32* b) {
    asm volatile(
        "mma.sync.aligned.m16n8k16.row.col.f32.f16.f16.f32 "
        "{%0,%1,%2,%3}, {%4,%5,%6,%7}, {%8,%9}, {%0,%1,%2,%3};"
        : "+f"(d[0]), "+f"(d[1]), "+f"(d[2]), "+f"(d[3])
        : "r"(a[0]), "r"(a[1]), "r"(a[2]), "r"(a[3]), "r"(b[0]), "r"(b[1]));
}
__device__ __forceinline__ ull pack4h(__half a, __half b, __half c, __half d) {
    u32 lo = ((u32)__half_as_ushort(b) << 16) | __half_as_ushort(a);
    u32 hi = ((u32)__half_as_ushort(d) << 16) | __half_as_ushort(c);
    return ((ull)hi << 32) | lo;
}
// byte offset of 4 fp16 at (row r, group-of-4 q); 256B rows, 16B-chunk XOR swizzle.
__device__ __forceinline__ u32 swz_off(int r, int q) {
    return ((u32)r << 8) + ((u32)(((q >> 1) ^ (r & 7))) << 4) + ((u32)(q & 1) << 3);
}
__device__ __forceinline__ void round_store_w(char* hi, int r, int q, float4 v) {
    *(ull*)(hi + swz_off(r, q)) = pack4h(
        __float2half_rn(v.x), __float2half_rn(v.y),
        __float2half_rn(v.z), __float2half_rn(v.w));
}
__device__ __forceinline__ __half2 as_h2(u32 v) { return *(__half2*)&v; }

// ---------------- graph preprocessing (CSR by dst, once per replay) ----------------
// dtype detection only (1 block). g_deg zeroing lives at the end of reorder_kernel.
__global__ void detect_kernel(const int* __restrict__ ei, int E) {
    __shared__ int s_any;
    if (threadIdx.x == 0) s_any = 0;
    __syncthreads();
    int nchk = E < 1024 ? E : 1024;
    int acc = 0;
    for (int e = threadIdx.x; e < nchk; e += blockDim.x)
        acc |= ei[2 * e + 1];
    if (acc) atomicOr(&s_any, 1);
    __syncthreads();
    if (threadIdx.x == 0) g_is64 = (s_any ? 0 : 1);
}

// histogram + (fused) x -> fp16 conversion
__global__ void hist_convert_kernel(const int* __restrict__ ei, int E,
                                    const float* __restrict__ x, int n) {
    int gid = blockIdx.x * blockDim.x + threadIdx.x;
    if (gid < E) {
        int dst = g_is64 ? ei[2 * (E + gid)] : ei[E + gid];
        atomicAdd(&g_deg[dst], 1);
    }
    int total4 = n * 32;
    int stride = gridDim.x * blockDim.x;
    uint2* xh2 = (uint2*)g_xh;
    for (int i = gid; i < total4; i += stride) {
        float4 v = ((const float4*)x)[i];
        __half2 a = __floats2half2_rn(v.x, v.y);
        __half2 b = __floats2half2_rn(v.z, v.w);
        uint2 u;
        u.x = *(u32*)&a;
        u.y = *(u32*)&b;
        xh2[i] = u;
    }
}

// scan stage A: per-block (1024 elems) sums
__global__ void scan_a_kernel(int n) {
    __shared__ int ssum[256];
    int tid = threadIdx.x;
    int base = blockIdx.x * 1024 + tid * 4;
    int s = 0;
#pragma unroll
    for (int j = 0; j < 4; ++j) {
        int i = base + j;
        if (i < n) s += g_deg[i];
    }
    ssum[tid] = s;
    __syncthreads();
    for (int off = 128; off > 0; off >>= 1) {
        if (tid < off) ssum[tid] += ssum[tid + off];
        __syncthreads();
    }
    if (tid == 0) g_bsum[blockIdx.x] = ssum[0];
}

// scan stage C: block-sum prefix + per-block exclusive scan; writes g_off/g_cursor.
__global__ void scan_c_kernel(int n) {
    __shared__ int sdata[256];
    __shared__ int s_boff;
    int tid = threadIdx.x;

    int partial = 0;
    for (int b = tid; b < (int)blockIdx.x; b += 256) partial += g_bsum[b];
    sdata[tid] = partial;
    __syncthreads();
    for (int off = 128; off > 0; off >>= 1) {
        if (tid < off) sdata[tid] += sdata[tid + off];
        __syncthreads();
    }
    if (tid == 0) s_boff = sdata[0];
    __syncthreads();

    int base = blockIdx.x * 1024 + tid * 4;
    int v[4];
    int tsum = 0;
#pragma unroll
    for (int j = 0; j < 4; ++j) {
        int i = base + j;
        v[j] = (i < n) ? g_deg[i] : 0;
        tsum += v[j];
    }
    sdata[tid] = tsum;
    __syncthreads();
    for (int off = 1; off < 256; off <<= 1) {
        int t = (tid >= off) ? sdata[tid - off] : 0;
        __syncthreads();
        sdata[tid] += t;
        __syncthreads();
    }
    int excl = sdata[tid] - tsum + s_boff;
#pragma unroll
    for (int j = 0; j < 4; ++j) {
        int i = base + j;
        if (i < n) {
            g_off[i] = excl;
            g_cursor[i] = excl;
            excl += v[j];
        }
    }
    if (blockIdx.x == gridDim.x - 1 && tid == 255)
        g_off[n] = s_boff + sdata[255];
}

// reorder edges by dst; re-zeroes g_deg to maintain the replay invariant.
__global__ void reorder_kernel(const int* __restrict__ ei, int E, int n) {
    int gid = blockIdx.x * blockDim.x + threadIdx.x;
    if (gid < n) g_deg[gid] = 0;    // deg is dead after scan; reset for next replay
    if (gid >= E) return;
    int src, dst;
    if (g_is64) {
        src = ei[2 * gid];
        dst = ei[2 * (E + gid)];
    } else {
        src = ei[gid];
        dst = ei[E + gid];
    }
    int pos = atomicAdd(&g_cursor[dst], 1);
    g_ssrc[pos] = src;
}

// ---------------- mean aggregation: one warp per TWO adjacent dst nodes ----------------
// Their CSR edge ranges are contiguous: [s0,e0) -> d0, [e0,e1) -> d1. The warp walks
// the merged range in 4-deep batches (no extra loads) and routes accumulation by a
// warp-uniform boundary compare. Doubles per-warp MLP coverage vs 1 node/warp.
__global__ void agg_kernel(const __half* __restrict__ feat, int n) {
    int gid = blockIdx.x * blockDim.x + threadIdx.x;
    int w = gid >> 5, lane = gid & 31;
    int d0 = w << 1;
    if (d0 >= n) return;
    int d1 = d0 + 1;
    int s0 = g_off[d0];
    int e0 = g_off[d0 + 1];
    int e1 = (d1 < n) ? g_off[d1 + 1] : e0;
    const uint2* f2 = (const uint2*)feat;
    float4 a0 = make_float4(0.f, 0.f, 0.f, 0.f);
    float4 a1 = a0;

#define ACC_SEL(U, P)                                                    \
    {                                                                    \
        float2 fa = __half22float2(as_h2((U).x));                        \
        float2 fb = __half22float2(as_h2((U).y));                        \
        if ((P) < e0) {                                                  \
            a0.x += fa.x; a0.y += fa.y; a0.z += fb.x; a0.w += fb.y;      \
        } else {                                                         \
            a1.x += fa.x; a1.y += fa.y; a1.z += fb.x; a1.w += fb.y;      \
        }                                                                \
    }

    int i = s0;
    for (; i + 3 < e1; i += 4) {
        int p0 = g_ssrc[i], p1 = g_ssrc[i + 1], p2 = g_ssrc[i + 2], p3 = g_ssrc[i + 3];
        uint2 u0 = f2[(size_t)p0 * 32 + lane];
        uint2 u1 = f2[(size_t)p1 * 32 + lane];
        uint2 u2 = f2[(size_t)p2 * 32 + lane];
        uint2 u3 = f2[(size_t)p3 * 32 + lane];
        ACC_SEL(u0, i)
        ACC_SEL(u1, i + 1)
        ACC_SEL(u2, i + 2)
        ACC_SEL(u3, i + 3)
    }
    if (i + 1 < e1) {
        int p0 = g_ssrc[i], p1 = g_ssrc[i + 1];
        uint2 u0 = f2[(size_t)p0 * 32 + lane];
        uint2 u1 = f2[(size_t)p1 * 32 + lane];
        ACC_SEL(u0, i)
        ACC_SEL(u1, i + 1)
        i += 2;
    }
    if (i < e1) {
        uint2 u0 = f2[(size_t)g_ssrc[i] * 32 + lane];
        ACC_SEL(u0, i)
    }
#undef ACC_SEL

    float inv0 = (e0 > s0) ? 1.0f / (float)(e0 - s0) : 0.0f;
    __half2 h0 = __floats2half2_rn(a0.x * inv0, a0.y * inv0);
    __half2 h1 = __floats2half2_rn(a0.z * inv0, a0.w * inv0);
    uint2 u;
    u.x = *(u32*)&h0;
    u.y = *(u32*)&h1;
    ((uint2*)g_aggh)[(size_t)d0 * 32 + lane] = u;
    if (d1 < n) {
        float inv1 = (e1 > e0) ? 1.0f / (float)(e1 - e0) : 0.0f;
        h0 = __floats2half2_rn(a1.x * inv1, a1.y * inv1);
        h1 = __floats2half2_rn(a1.z * inv1, a1.w * inv1);
        u.x = *(u32*)&h0;
        u.y = *(u32*)&h1;
        ((uint2*)g_aggh)[(size_t)d1 * 32 + lane] = u;
    }
}

// ---------------- HMMA fused SAGE layer (all-fp16, 2 CTAs/SM) ----------------
// out = act( aggh @ Wl^T + bl + A2h @ Wr^T )
__device__ __forceinline__ void mma_pass1(u32 abh, u32 wbh,
                                          float acc[2][4][4],
                                          const u32* rowA256, u32 rowA7, u32 kbitA,
                                          const u32* rw256, const u32* rw7, u32 kgrpW) {
#pragma unroll
    for (int ks = 0; ks < 8; ++ks) {
        u32 ks2 = (u32)(ks << 1);
        u32 ah[2][4], wh[2][4];
        u32 ca = ((ks2 | kbitA) ^ rowA7) << 4;
#pragma unroll
        for (int mt = 0; mt < 2; ++mt)
            ldsm4(ah[mt], abh + rowA256[mt] + ca);
#pragma unroll
        for (int nt2 = 0; nt2 < 2; ++nt2) {
            u32 cw = ((ks2 | kgrpW) ^ rw7[nt2]) << 4;
            ldsm4(wh[nt2], wbh + rw256[nt2] + cw);
        }
#pragma unroll
        for (int mt = 0; mt < 2; ++mt)
#pragma unroll
            for (int nt = 0; nt < 4; ++nt)
                mma16816(acc[mt][nt], ah[mt], &wh[nt >> 1][(nt & 1) * 2]);
    }
}

__global__ void __launch_bounds__(256, 2)
layer_kernel(const __half* __restrict__ A2h,
             const float* __restrict__ Wl,
             const float* __restrict__ Wr,
             const float* __restrict__ bl,
             float* __restrict__ outf,
             __half* __restrict__ outh,
             int n, int apply_sig, int ntiles) {
    extern __shared__ char sm[];
    u32 smb = smem_u32(sm);
    float* sBias = (float*)(sm + OFF_BIAS);
    int tid = threadIdx.x, wid = tid >> 5, lane = tid & 31;
    int warp_m = wid & 1, warp_n = wid >> 1;

    // Round both weight matrices ([n][k], 128x128) to fp16.
    for (int idx = tid; idx < 128 * 32; idx += 256) {
        int r = idx >> 5, q = idx & 31;
        round_store_w(sm + OFF_WLH, r, q, ((const float4*)Wl)[idx]);
        round_store_w(sm + OFF_WRH, r, q, ((const float4*)Wr)[idx]);
    }
    if (tid < 128) sBias[tid] = bl[tid];

    // ldmatrix address precomputation.
    u32 rowA256[2], rowA7;
    {
        int ra0 = warp_m * 32 + (lane & 15);
        rowA256[0] = (u32)(ra0 << 8);
        rowA256[1] = (u32)((ra0 + 16) << 8);
        rowA7 = (u32)(ra0 & 7);
    }
    u32 kbitA = (u32)(lane >> 4);
    u32 rw256[2], rw7[2];
    u32 kgrpW = (u32)((lane >> 3) & 1);
    {
        int base = warp_n * 32 + (lane & 7) + ((lane >> 4) << 3);
#pragma unroll
        for (int nt2 = 0; nt2 < 2; ++nt2) {
            int rw = base + nt2 * 16;
            rw256[nt2] = (u32)(rw << 8);
            rw7[nt2] = (u32)(rw & 7);
        }
    }
    int g = lane >> 2, c2 = (lane & 3) * 2;

    const uint2* ag2 = (const uint2*)g_aggh;
    const uint2* x2 = (const uint2*)A2h;
    const uint2 uz = make_uint2(0u, 0u);

    uint2 va[8], vx[8];
    int tile = blockIdx.x;

    if (tile < ntiles) {
        int row0 = tile * BM;
#pragma unroll
        for (int j = 0; j < 8; ++j) {
            int idx = tid + j * 256;
            int row = row0 + (idx >> 5);
            va[j] = (row < n) ? ag2[(size_t)row * 32 + (idx & 31)] : uz;
            vx[j] = (row < n) ? x2[(size_t)row * 32 + (idx & 31)] : uz;
        }
    }

    for (; tile < ntiles; tile += gridDim.x) {
        __syncthreads();   // prior tile MMA done reading A buffers (covers W on 1st)
#pragma unroll
        for (int j = 0; j < 8; ++j) {
            int idx = tid + j * 256;
            int r = idx >> 5, q = idx & 31;
            u32 off = swz_off(r, q);
            *(uint2*)(sm + OFF_AGH + off) = va[j];
            *(uint2*)(sm + OFF_AXH + off) = vx[j];
        }
        __syncthreads();

        // Prefetch next tile's A registers; LDG latency hides under MMA below.
        int next = tile + gridDim.x;
        if (next < ntiles) {
            int row0 = next * BM;
#pragma unroll
            for (int j = 0; j < 8; ++j) {
                int idx = tid + j * 256;
                int row = row0 + (idx >> 5);
                va[j] = (row < n) ? ag2[(size_t)row * 32 + (idx & 31)] : uz;
                vx[j] = (row < n) ? x2[(size_t)row * 32 + (idx & 31)] : uz;
            }
        }

        float acc[2][4][4];
#pragma unroll
        for (int mt = 0; mt < 2; ++mt)
#pragma unroll
            for (int nt = 0; nt < 4; ++nt)
#pragma unroll
                for (int i = 0; i < 4; ++i) acc[mt][nt][i] = 0.f;

        mma_pass1(smb + OFF_AGH, smb + OFF_WLH,
                  acc, rowA256, rowA7, kbitA, rw256, rw7, kgrpW);
        mma_pass1(smb + OFF_AXH, smb + OFF_WRH,
                  acc, rowA256, rowA7, kbitA, rw256, rw7, kgrpW);

        // epilogue
        int row0 = tile * BM;
#pragma unroll
        for (int mt = 0; mt < 2; ++mt) {
#pragma unroll
            for (int half = 0; half < 2; ++half) {
                int row = row0 + warp_m * 32 + mt * 16 + g + half * 8;
                if (row < n) {
#pragma unroll
                    for (int nt = 0; nt < 4; ++nt) {
                        int col = warp_n * 32 + nt * 8 + c2;
                        float2 v;
                        v.x = acc[mt][nt][half * 2 + 0] + sBias[col];
                        v.y = acc[mt][nt][half * 2 + 1] + sBias[col + 1];
                        if (apply_sig) {
                            v.x = 1.0f / (1.0f + __expf(-v.x));
                            v.y = 1.0f / (1.0f + __expf(-v.y));
                            __half2 hv = __floats2half2_rn(v.x, v.y);
                            *(__half2*)(outh + (size_t)row * CH + col) = hv;
                        } else {
                            *(float2*)(outf + (size_t)row * CH + col) = v;
                        }
                    }
                }
            }
        }
    }
}

extern "C" void kernel_launch(void* const* d_in, const int* in_sizes, int n_in,
                              void* d_out, int out_size) {
    const float* x   = (const float*)d_in[0];
    const int*   ei  = (const int*)d_in[1];
    const float* W1l = (const float*)d_in[2];
    const float* b1l = (const float*)d_in[3];
    const float* W1r = (const float*)d_in[4];
    const float* W2l = (const float*)d_in[5];
    const float* b2l = (const float*)d_in[6];
    const float* W2r = (const float*)d_in[7];
    float* out = (float*)d_out;

    int n = in_sizes[0] / CH;   // 100000
    int E = in_sizes[1] / 2;    // 625000
    if (E > EMAX) E = EMAX;

    __half* xh_ptr = nullptr;
    __half* hh_ptr = nullptr;
    cudaGetSymbolAddress((void**)&xh_ptr, g_xh);
    cudaGetSymbolAddress((void**)&hh_ptr, g_hh);

    cudaFuncSetAttribute(layer_kernel,
                         cudaFuncAttributeMaxDynamicSharedMemorySize, SMEM_TOTAL);

    int ntiles = (n + BM - 1) / BM;
    int grid_layer = ntiles < 296 ? ntiles : 296;   // 2 CTAs/SM
    int grid_edge = (E + 255) / 256;
    int nblk = (n + 1023) / 1024;
    int npairs = (n + 1) / 2;
    int grid_agg = (int)(((long long)npairs * 32 + 255) / 256);

    // CSR preprocessing + x->fp16 (once; reused by both layers).
    // g_deg zero-invariant: .bss on first run, re-zeroed by reorder_kernel.
    detect_kernel<<<1, 256>>>(ei, E);
    hist_convert_kernel<<<grid_edge, 256>>>(ei, E, x, n);
    scan_a_kernel<<<nblk, 256>>>(n);
    scan_c_kernel<<<nblk, 256>>>(n);
    reorder_kernel<<<grid_edge, 256>>>(ei, E, n);

    // Layer 1
    agg_kernel<<<grid_agg, 256>>>(xh_ptr, n);
    layer_kernel<<<grid_layer, 256, SMEM_TOTAL>>>(xh_ptr, W1l, W1r, b1l,
                                                  nullptr, hh_ptr, n, 1, ntiles);

    // Layer 2
    agg_kernel<<<grid_agg, 256>>>(hh_ptr, n);
    layer_kernel<<<grid_layer, 256, SMEM_TOTAL>>>(hh_ptr, W2l, W2r, b2l,
                                                  out, nullptr, n, 0, ntiles);
}